// round 1
// baseline (speedup 1.0000x reference)
#include <cuda_runtime.h>
#include <math.h>

// Problem shape (fixed by reference): B=4, S=2048, D=1024
#define BATCH 4
#define SEQ   2048
#define DIM   1024

// SGEMM tiling
#define BM 128
#define BN 128
#define BK 8
#define NTHREADS 256

// Scratch (allocation-free: __device__ globals)
__device__ float g_q[BATCH * SEQ * DIM];
__device__ float g_k[BATCH * SEQ * DIM];
__device__ float g_v[BATCH * SEQ * DIM];
__device__ float g_s[(size_t)BATCH * SEQ * SEQ];

// ---------------------------------------------------------------------------
// NN SGEMM: C[M,N] = A[M,K] @ B[K,N], all row-major. Optional causal K-limit:
// if klimit_causal != 0, only accumulate k0 < min(K, r0+BM) (PV stage: P rows
// in tile [r0, r0+BM) have zero weight beyond key r0+BM-1).
// Grid: (N/BN, M/BM, batch). Batch strides passed explicitly (0 for proj).
// ---------------------------------------------------------------------------
__global__ __launch_bounds__(NTHREADS)
void sgemm_nn_kernel(const float* __restrict__ A,
                     const float* __restrict__ B,
                     float* __restrict__ C,
                     int N, int K,
                     size_t strideA, size_t strideB, size_t strideC,
                     int klimit_causal)
{
    __shared__ float As[BK][BM];
    __shared__ float Bs[BK][BN];

    const int tid = threadIdx.x;
    const int r0 = blockIdx.y * BM;
    const int c0 = blockIdx.x * BN;

    A += (size_t)blockIdx.z * strideA;
    B += (size_t)blockIdx.z * strideB;
    C += (size_t)blockIdx.z * strideC;

    // A tile: 128 rows x 8 cols, each thread loads one float4 along K
    const int a_row = tid >> 1;
    const int a_col = (tid & 1) << 2;
    // B tile: 8 rows x 128 cols, each thread loads one float4 along N
    const int b_row = tid >> 5;
    const int b_col = (tid & 31) << 2;

    const int ty = tid >> 4;   // 0..15
    const int tx = tid & 15;   // 0..15

    float acc[8][8];
#pragma unroll
    for (int i = 0; i < 8; i++)
#pragma unroll
        for (int j = 0; j < 8; j++) acc[i][j] = 0.f;

    const int kend = klimit_causal ? min(K, r0 + BM) : K;

    for (int k0 = 0; k0 < kend; k0 += BK) {
        float4 av = *reinterpret_cast<const float4*>(
            &A[(size_t)(r0 + a_row) * K + (k0 + a_col)]);
        As[a_col + 0][a_row] = av.x;
        As[a_col + 1][a_row] = av.y;
        As[a_col + 2][a_row] = av.z;
        As[a_col + 3][a_row] = av.w;
        *reinterpret_cast<float4*>(&Bs[b_row][b_col]) =
            *reinterpret_cast<const float4*>(
                &B[(size_t)(k0 + b_row) * N + (c0 + b_col)]);
        __syncthreads();
#pragma unroll
        for (int k = 0; k < BK; k++) {
            float ar[8], br[8];
            *reinterpret_cast<float4*>(&ar[0]) =
                *reinterpret_cast<float4*>(&As[k][ty * 4]);
            *reinterpret_cast<float4*>(&ar[4]) =
                *reinterpret_cast<float4*>(&As[k][64 + ty * 4]);
            *reinterpret_cast<float4*>(&br[0]) =
                *reinterpret_cast<float4*>(&Bs[k][tx * 4]);
            *reinterpret_cast<float4*>(&br[4]) =
                *reinterpret_cast<float4*>(&Bs[k][64 + tx * 4]);
#pragma unroll
            for (int i = 0; i < 8; i++)
#pragma unroll
                for (int j = 0; j < 8; j++)
                    acc[i][j] = fmaf(ar[i], br[j], acc[i][j]);
        }
        __syncthreads();
    }

#pragma unroll
    for (int i = 0; i < 8; i++) {
        const int moff = (i < 4) ? (ty * 4 + i) : (64 + ty * 4 + (i - 4));
        float* crow = &C[(size_t)(r0 + moff) * N + c0];
        float4 v0 = make_float4(acc[i][0], acc[i][1], acc[i][2], acc[i][3]);
        float4 v1 = make_float4(acc[i][4], acc[i][5], acc[i][6], acc[i][7]);
        *reinterpret_cast<float4*>(&crow[tx * 4])      = v0;
        *reinterpret_cast<float4*>(&crow[64 + tx * 4]) = v1;
    }
}

// ---------------------------------------------------------------------------
// NT SGEMM for scores: S[b,i,j] = (1/32) * sum_d Q[b,i,d]*K[b,j,d],
// causal mask (j > i -> -inf). Fully-masked tiles (bx > by) skipped entirely
// (softmax never reads j > i, so those tiles are never consumed).
// Grid: (SEQ/BN, SEQ/BM, BATCH)
// ---------------------------------------------------------------------------
__global__ __launch_bounds__(NTHREADS)
void scores_kernel(const float* __restrict__ Q,
                   const float* __restrict__ Kmat,
                   float* __restrict__ S)
{
    if (blockIdx.x > blockIdx.y) return;  // fully masked tile

    __shared__ float As[BK][BM];
    __shared__ float Bs[BK][BN];

    const int tid = threadIdx.x;
    const int r0 = blockIdx.y * BM;
    const int c0 = blockIdx.x * BN;

    const float* A = Q    + (size_t)blockIdx.z * SEQ * DIM;
    const float* B = Kmat + (size_t)blockIdx.z * SEQ * DIM;
    float*       C = g_s  + (size_t)blockIdx.z * SEQ * SEQ;
    (void)S;

    const int t_row = tid >> 1;
    const int t_col = (tid & 1) << 2;

    const int ty = tid >> 4;
    const int tx = tid & 15;

    float acc[8][8];
#pragma unroll
    for (int i = 0; i < 8; i++)
#pragma unroll
        for (int j = 0; j < 8; j++) acc[i][j] = 0.f;

    for (int k0 = 0; k0 < DIM; k0 += BK) {
        float4 av = *reinterpret_cast<const float4*>(
            &A[(size_t)(r0 + t_row) * DIM + (k0 + t_col)]);
        As[t_col + 0][t_row] = av.x;
        As[t_col + 1][t_row] = av.y;
        As[t_col + 2][t_row] = av.z;
        As[t_col + 3][t_row] = av.w;
        float4 bv = *reinterpret_cast<const float4*>(
            &B[(size_t)(c0 + t_row) * DIM + (k0 + t_col)]);
        Bs[t_col + 0][t_row] = bv.x;
        Bs[t_col + 1][t_row] = bv.y;
        Bs[t_col + 2][t_row] = bv.z;
        Bs[t_col + 3][t_row] = bv.w;
        __syncthreads();
#pragma unroll
        for (int k = 0; k < BK; k++) {
            float ar[8], br[8];
            *reinterpret_cast<float4*>(&ar[0]) =
                *reinterpret_cast<float4*>(&As[k][ty * 4]);
            *reinterpret_cast<float4*>(&ar[4]) =
                *reinterpret_cast<float4*>(&As[k][64 + ty * 4]);
            *reinterpret_cast<float4*>(&br[0]) =
                *reinterpret_cast<float4*>(&Bs[k][tx * 4]);
            *reinterpret_cast<float4*>(&br[4]) =
                *reinterpret_cast<float4*>(&Bs[k][64 + tx * 4]);
#pragma unroll
            for (int i = 0; i < 8; i++)
#pragma unroll
                for (int j = 0; j < 8; j++)
                    acc[i][j] = fmaf(ar[i], br[j], acc[i][j]);
        }
        __syncthreads();
    }

    const float scale = 0.03125f;  // 1/sqrt(1024)
    const float NEGINF = -INFINITY;
#pragma unroll
    for (int i = 0; i < 8; i++) {
        const int moff = (i < 4) ? (ty * 4 + i) : (64 + ty * 4 + (i - 4));
        const int gi = r0 + moff;
        float* crow = &C[(size_t)gi * SEQ + c0];
#pragma unroll
        for (int half = 0; half < 2; half++) {
            const int nbase = half * 64 + tx * 4;
            float4 v;
            float w0 = acc[i][half * 4 + 0] * scale;
            float w1 = acc[i][half * 4 + 1] * scale;
            float w2 = acc[i][half * 4 + 2] * scale;
            float w3 = acc[i][half * 4 + 3] * scale;
            v.x = (c0 + nbase + 0 > gi) ? NEGINF : w0;
            v.y = (c0 + nbase + 1 > gi) ? NEGINF : w1;
            v.z = (c0 + nbase + 2 > gi) ? NEGINF : w2;
            v.w = (c0 + nbase + 3 > gi) ? NEGINF : w3;
            *reinterpret_cast<float4*>(&crow[nbase]) = v;
        }
    }
}

// ---------------------------------------------------------------------------
// Causal row softmax in-place on g_s. One block per row; valid length L=i+1,
// zero-fill the rest so the PV GEMM can run dense up to its causal K-limit.
// Grid: (BATCH*SEQ)
// ---------------------------------------------------------------------------
__global__ __launch_bounds__(256)
void softmax_kernel(float* __restrict__ S)
{
    const int row = blockIdx.x;              // 0 .. BATCH*SEQ-1
    const int i = row & (SEQ - 1);
    float* srow = S + (size_t)row * SEQ;
    const int L = i + 1;

    __shared__ float buf[SEQ];
    __shared__ float red[256];
    const int tid = threadIdx.x;

    float m = -INFINITY;
    for (int j = tid; j < L; j += 256) {
        float v = srow[j];
        buf[j] = v;
        m = fmaxf(m, v);
    }
    red[tid] = m;
    __syncthreads();
    for (int s = 128; s > 0; s >>= 1) {
        if (tid < s) red[tid] = fmaxf(red[tid], red[tid + s]);
        __syncthreads();
    }
    m = red[0];
    __syncthreads();

    float sum = 0.f;
    for (int j = tid; j < L; j += 256) {
        float e = __expf(buf[j] - m);
        buf[j] = e;
        sum += e;
    }
    red[tid] = sum;
    __syncthreads();
    for (int s = 128; s > 0; s >>= 1) {
        if (tid < s) red[tid] += red[tid + s];
        __syncthreads();
    }
    const float inv = 1.0f / red[0];
    __syncthreads();

    for (int j = tid; j < L; j += 256) srow[j] = buf[j] * inv;
    for (int j = L + tid; j < SEQ; j += 256) srow[j] = 0.f;
}

// ---------------------------------------------------------------------------
extern "C" void kernel_launch(void* const* d_in, const int* in_sizes, int n_in,
                              void* d_out, int out_size)
{
    const float* x  = (const float*)d_in[0];
    const float* Wq = (const float*)d_in[1];
    const float* Wk = (const float*)d_in[2];
    const float* Wv = (const float*)d_in[3];
    float* out = (float*)d_out;

    float *q, *k, *v, *s;
    cudaGetSymbolAddress((void**)&q, g_q);
    cudaGetSymbolAddress((void**)&k, g_k);
    cudaGetSymbolAddress((void**)&v, g_v);
    cudaGetSymbolAddress((void**)&s, g_s);

    // 1) QKV projections: [B*S, D] @ [D, D]
    {
        dim3 grid(DIM / BN, (BATCH * SEQ) / BM, 1);
        sgemm_nn_kernel<<<grid, NTHREADS>>>(x, Wq, q, DIM, DIM, 0, 0, 0, 0);
        sgemm_nn_kernel<<<grid, NTHREADS>>>(x, Wk, k, DIM, DIM, 0, 0, 0, 0);
        sgemm_nn_kernel<<<grid, NTHREADS>>>(x, Wv, v, DIM, DIM, 0, 0, 0, 0);
    }

    // 2) Causal scores: S = (Q @ K^T) / 32, masked
    {
        dim3 grid(SEQ / BN, SEQ / BM, BATCH);
        scores_kernel<<<grid, NTHREADS>>>(q, k, s);
    }

    // 3) Row softmax (causal, in-place, zero-fill masked region)
    softmax_kernel<<<BATCH * SEQ, 256>>>(s);

    // 4) O = P @ V with causal K-limit per row tile
    {
        dim3 grid(DIM / BN, SEQ / BM, BATCH);
        sgemm_nn_kernel<<<grid, NTHREADS>>>(
            s, v, out, DIM, SEQ,
            (size_t)SEQ * SEQ, (size_t)SEQ * DIM, (size_t)SEQ * DIM,
            /*klimit_causal=*/1);
    }
}

// round 3
// speedup vs baseline: 3.2942x; 3.2942x over previous
#include <cuda_runtime.h>
#include <math.h>

// Problem shape (fixed by reference): B=4, S=2048, D=1024
#define BATCH 4
#define SEQ   2048
#define DIM   1024

// Tiling
#define BM 128
#define BN 128
#define BK 32
#define NTHREADS 256

#define ASTRIDE 36            // 128x32 tile rows padded: (4g+tig) bank pattern, conflict-free
#define BSTRIDE_NN 136        // 32x128 tile rows padded: (8k+n) bank pattern, conflict-free
#define ASZ (BM * ASTRIDE)    // 4608 floats per stage
#define BSZ_NN (BK * BSTRIDE_NN)  // 4352
#define BSZ_NT (BN * ASTRIDE)     // 4608
#define SMEM_NN ((2 * (ASZ + BSZ_NN)) * 4)  // 71680 B
#define SMEM_NT ((2 * (ASZ + BSZ_NT)) * 4)  // 73728 B

// Scratch (allocation-free: __device__ globals)
__device__ float g_q[BATCH * SEQ * DIM];
__device__ float g_k[BATCH * SEQ * DIM];
__device__ float g_v[BATCH * SEQ * DIM];
__device__ float g_s[(size_t)BATCH * SEQ * SEQ];

// ---------------------------------------------------------------------------
// helpers
// ---------------------------------------------------------------------------
__device__ __forceinline__ unsigned sptr(const void* p) {
    return (unsigned)__cvta_generic_to_shared(p);
}
__device__ __forceinline__ void cpa16(void* s, const void* g) {
    asm volatile("cp.async.cg.shared.global [%0], [%1], 16;\n"
                 :: "r"(sptr(s)), "l"(g));
}
__device__ __forceinline__ void cp_commit() {
    asm volatile("cp.async.commit_group;\n");
}
__device__ __forceinline__ void cp_wait1() {
    asm volatile("cp.async.wait_group 1;\n");
}
__device__ __forceinline__ unsigned f2t(float x) {
    unsigned u;
    asm("cvt.rna.tf32.f32 %0, %1;\n" : "=r"(u) : "f"(x));
    return u;
}
__device__ __forceinline__ void mma_tf32(float c[4], const unsigned a[4],
                                         const unsigned b[2]) {
    asm volatile(
        "mma.sync.aligned.m16n8k8.row.col.f32.tf32.tf32.f32 "
        "{%0,%1,%2,%3}, {%4,%5,%6,%7}, {%8,%9}, {%0,%1,%2,%3};\n"
        : "+f"(c[0]), "+f"(c[1]), "+f"(c[2]), "+f"(c[3])
        : "r"(a[0]), "r"(a[1]), "r"(a[2]), "r"(a[3]), "r"(b[0]), "r"(b[1]));
}

// Load a 128-row x 32-col fp32 tile (A, or NT-mode B) into padded smem.
__device__ __forceinline__ void ldg_tile128x32(float* dst, const float* g, int ld) {
#pragma unroll
    for (int p = 0; p < 4; p++) {
        int i = threadIdx.x + p * 256;
        int row = i >> 3;
        int c4 = (i & 7) << 2;
        cpa16(dst + row * ASTRIDE + c4, g + (size_t)row * ld + c4);
    }
}
// Load a 32-row x 128-col fp32 tile (NN-mode B) into padded smem.
__device__ __forceinline__ void ldg_tile32x128(float* dst, const float* g, int ld) {
#pragma unroll
    for (int p = 0; p < 4; p++) {
        int i = threadIdx.x + p * 256;
        int row = i >> 5;
        int c4 = (i & 31) << 2;
        cpa16(dst + row * BSTRIDE_NN + c4, g + (size_t)row * ld + c4);
    }
}

// One BK=32 stage of warp-level mma. Warp computes a 64x32 tile:
// 4 m-frags (m16) x 4 n-frags (n8), k in 4 steps of 8.
template <bool NT>
__device__ __forceinline__ void compute_stage(const float* __restrict__ As,
                                              const float* __restrict__ Bs,
                                              float (&c)[16][4],
                                              int g, int tig, int wm0, int wn0) {
#pragma unroll
    for (int kk = 0; kk < BK; kk += 8) {
        unsigned a[4][4], b[4][2];
#pragma unroll
        for (int mi = 0; mi < 4; mi++) {
            const float* ap = As + (wm0 + mi * 16 + g) * ASTRIDE + kk + tig;
            a[mi][0] = f2t(ap[0]);
            a[mi][1] = f2t(ap[8 * ASTRIDE]);
            a[mi][2] = f2t(ap[4]);
            a[mi][3] = f2t(ap[8 * ASTRIDE + 4]);
        }
#pragma unroll
        for (int ni = 0; ni < 4; ni++) {
            int col = wn0 + ni * 8 + g;
            if (NT) {
                const float* bp = Bs + col * ASTRIDE + kk + tig;
                b[ni][0] = f2t(bp[0]);
                b[ni][1] = f2t(bp[4]);
            } else {
                const float* bp = Bs + (kk + tig) * BSTRIDE_NN + col;
                b[ni][0] = f2t(bp[0]);
                b[ni][1] = f2t(bp[4 * BSTRIDE_NN]);
            }
        }
#pragma unroll
        for (int mi = 0; mi < 4; mi++)
#pragma unroll
            for (int ni = 0; ni < 4; ni++)
                mma_tf32(c[mi * 4 + ni], a[mi], b[ni]);
    }
}

// ---------------------------------------------------------------------------
// Fused QKV projection: grid (24, 64). bx>>3 selects {Wq,Wk,Wv} -> {g_q,g_k,g_v}
// C[8192,1024] = x[8192,1024] @ W[1024,1024]
// ---------------------------------------------------------------------------
__global__ void __launch_bounds__(NTHREADS)
proj_kernel(const float* __restrict__ x, const float* __restrict__ Wq,
            const float* __restrict__ Wk, const float* __restrict__ Wv) {
    extern __shared__ float sm[];
    float* As = sm;
    float* Bs = sm + 2 * ASZ;

    const int which = blockIdx.x >> 3;
    const int c0 = (blockIdx.x & 7) * BN;
    const int r0 = blockIdx.y * BM;
    const float* W = (which == 0) ? Wq : (which == 1) ? Wk : Wv;
    float* C = (which == 0) ? g_q : (which == 1) ? g_k : g_v;

    const int lane = threadIdx.x & 31, warp = threadIdx.x >> 5;
    const int g = lane >> 2, tig = lane & 3;
    const int wm0 = (warp >> 2) * 64, wn0 = (warp & 3) * 32;

    float c[16][4];
#pragma unroll
    for (int f = 0; f < 16; f++)
#pragma unroll
        for (int j = 0; j < 4; j++) c[f][j] = 0.f;

    const int T = DIM / BK;  // 32
    ldg_tile128x32(As, x + (size_t)r0 * DIM, DIM);
    ldg_tile32x128(Bs, W + c0, DIM);
    cp_commit();
    ldg_tile128x32(As + ASZ, x + (size_t)r0 * DIM + BK, DIM);
    ldg_tile32x128(Bs + BSZ_NN, W + (size_t)BK * DIM + c0, DIM);
    cp_commit();

    for (int t = 0; t < T; t++) {
        cp_wait1();
        __syncthreads();
        compute_stage<false>(As + (t & 1) * ASZ, Bs + (t & 1) * BSZ_NN, c, g, tig, wm0, wn0);
        __syncthreads();
        if (t + 2 < T) {
            const int k0 = (t + 2) * BK;
            ldg_tile128x32(As + (t & 1) * ASZ, x + (size_t)r0 * DIM + k0, DIM);
            ldg_tile32x128(Bs + (t & 1) * BSZ_NN, W + (size_t)k0 * DIM + c0, DIM);
        }
        cp_commit();
    }

#pragma unroll
    for (int mi = 0; mi < 4; mi++)
#pragma unroll
        for (int ni = 0; ni < 4; ni++) {
            const float* f = c[mi * 4 + ni];
            const int row = r0 + wm0 + mi * 16 + g;
            const int col = c0 + wn0 + ni * 8 + tig * 2;
            *(float2*)&C[(size_t)row * DIM + col] = make_float2(f[0], f[1]);
            *(float2*)&C[(size_t)(row + 8) * DIM + col] = make_float2(f[2], f[3]);
        }
}

// ---------------------------------------------------------------------------
// Causal scores: S[b,i,j] = (Q_i . K_j)/32, j>i -> -inf. NT mode.
// grid (16, 16, 4); fully-masked tiles (bx>by) skipped.
// ---------------------------------------------------------------------------
__global__ void __launch_bounds__(NTHREADS)
scores_kernel() {
    if (blockIdx.x > blockIdx.y) return;

    extern __shared__ float sm[];
    float* As = sm;
    float* Bs = sm + 2 * ASZ;

    const int c0 = blockIdx.x * BN;
    const int r0 = blockIdx.y * BM;
    const float* Q = g_q + (size_t)blockIdx.z * SEQ * DIM;
    const float* K = g_k + (size_t)blockIdx.z * SEQ * DIM;
    float* C = g_s + (size_t)blockIdx.z * SEQ * SEQ;

    const int lane = threadIdx.x & 31, warp = threadIdx.x >> 5;
    const int g = lane >> 2, tig = lane & 3;
    const int wm0 = (warp >> 2) * 64, wn0 = (warp & 3) * 32;

    float c[16][4];
#pragma unroll
    for (int f = 0; f < 16; f++)
#pragma unroll
        for (int j = 0; j < 4; j++) c[f][j] = 0.f;

    const int T = DIM / BK;  // 32
    ldg_tile128x32(As, Q + (size_t)r0 * DIM, DIM);
    ldg_tile128x32(Bs, K + (size_t)c0 * DIM, DIM);
    cp_commit();
    ldg_tile128x32(As + ASZ, Q + (size_t)r0 * DIM + BK, DIM);
    ldg_tile128x32(Bs + BSZ_NT, K + (size_t)c0 * DIM + BK, DIM);
    cp_commit();

    for (int t = 0; t < T; t++) {
        cp_wait1();
        __syncthreads();
        compute_stage<true>(As + (t & 1) * ASZ, Bs + (t & 1) * BSZ_NT, c, g, tig, wm0, wn0);
        __syncthreads();
        if (t + 2 < T) {
            const int k0 = (t + 2) * BK;
            ldg_tile128x32(As + (t & 1) * ASZ, Q + (size_t)r0 * DIM + k0, DIM);
            ldg_tile128x32(Bs + (t & 1) * BSZ_NT, K + (size_t)c0 * DIM + k0, DIM);
        }
        cp_commit();
    }

    const float scale = 0.03125f;  // 1/sqrt(1024)
    const float NEGINF = -INFINITY;
#pragma unroll
    for (int mi = 0; mi < 4; mi++)
#pragma unroll
        for (int ni = 0; ni < 4; ni++) {
            const float* f = c[mi * 4 + ni];
            const int col = c0 + wn0 + ni * 8 + tig * 2;
#pragma unroll
            for (int h = 0; h < 2; h++) {
                const int row = r0 + wm0 + mi * 16 + g + h * 8;
                float v0 = (col > row) ? NEGINF : f[h * 2 + 0] * scale;
                float v1 = (col + 1 > row) ? NEGINF : f[h * 2 + 1] * scale;
                *(float2*)&C[(size_t)row * SEQ + col] = make_float2(v0, v1);
            }
        }
}

// ---------------------------------------------------------------------------
// O = P @ V with causal K-limit per row tile. NN mode, grid (8, 16, 4).
// ---------------------------------------------------------------------------
__global__ void __launch_bounds__(NTHREADS)
pv_kernel(float* __restrict__ out) {
    extern __shared__ float sm[];
    float* As = sm;
    float* Bs = sm + 2 * ASZ;

    const int c0 = blockIdx.x * BN;
    const int r0 = blockIdx.y * BM;
    const float* P = g_s + (size_t)blockIdx.z * SEQ * SEQ;
    const float* V = g_v + (size_t)blockIdx.z * SEQ * DIM;
    float* C = out + (size_t)blockIdx.z * SEQ * DIM;

    const int lane = threadIdx.x & 31, warp = threadIdx.x >> 5;
    const int g = lane >> 2, tig = lane & 3;
    const int wm0 = (warp >> 2) * 64, wn0 = (warp & 3) * 32;

    float c[16][4];
#pragma unroll
    for (int f = 0; f < 16; f++)
#pragma unroll
        for (int j = 0; j < 4; j++) c[f][j] = 0.f;

    const int T = (r0 + BM) / BK;  // causal K-limit, >= 4
    ldg_tile128x32(As, P + (size_t)r0 * SEQ, SEQ);
    ldg_tile32x128(Bs, V + c0, DIM);
    cp_commit();
    ldg_tile128x32(As + ASZ, P + (size_t)r0 * SEQ + BK, SEQ);
    ldg_tile32x128(Bs + BSZ_NN, V + (size_t)BK * DIM + c0, DIM);
    cp_commit();

    for (int t = 0; t < T; t++) {
        cp_wait1();
        __syncthreads();
        compute_stage<false>(As + (t & 1) * ASZ, Bs + (t & 1) * BSZ_NN, c, g, tig, wm0, wn0);
        __syncthreads();
        if (t + 2 < T) {
            const int k0 = (t + 2) * BK;
            ldg_tile128x32(As + (t & 1) * ASZ, P + (size_t)r0 * SEQ + k0, SEQ);
            ldg_tile32x128(Bs + (t & 1) * BSZ_NN, V + (size_t)k0 * DIM + c0, DIM);
        }
        cp_commit();
    }

#pragma unroll
    for (int mi = 0; mi < 4; mi++)
#pragma unroll
        for (int ni = 0; ni < 4; ni++) {
            const float* f = c[mi * 4 + ni];
            const int row = r0 + wm0 + mi * 16 + g;
            const int col = c0 + wn0 + ni * 8 + tig * 2;
            *(float2*)&C[(size_t)row * DIM + col] = make_float2(f[0], f[1]);
            *(float2*)&C[(size_t)(row + 8) * DIM + col] = make_float2(f[2], f[3]);
        }
}

// ---------------------------------------------------------------------------
// Causal row softmax in-place on g_s; zero-fill masked tail so PV runs dense.
// ---------------------------------------------------------------------------
__global__ void __launch_bounds__(256)
softmax_kernel() {
    const int row = blockIdx.x;
    const int i = row & (SEQ - 1);
    float* srow = g_s + (size_t)row * SEQ;
    const int L = i + 1;

    __shared__ float buf[SEQ];
    __shared__ float red[256];
    const int tid = threadIdx.x;

    float m = -INFINITY;
    for (int j = tid; j < L; j += 256) {
        float v = srow[j];
        buf[j] = v;
        m = fmaxf(m, v);
    }
    red[tid] = m;
    __syncthreads();
    for (int s = 128; s > 0; s >>= 1) {
        if (tid < s) red[tid] = fmaxf(red[tid], red[tid + s]);
        __syncthreads();
    }
    m = red[0];
    __syncthreads();

    float sum = 0.f;
    for (int j = tid; j < L; j += 256) {
        float e = __expf(buf[j] - m);
        buf[j] = e;
        sum += e;
    }
    red[tid] = sum;
    __syncthreads();
    for (int s = 128; s > 0; s >>= 1) {
        if (tid < s) red[tid] += red[tid + s];
        __syncthreads();
    }
    const float inv = 1.0f / red[0];
    __syncthreads();

    for (int j = tid; j < L; j += 256) srow[j] = buf[j] * inv;
    for (int j = L + tid; j < SEQ; j += 256) srow[j] = 0.f;
}

// ---------------------------------------------------------------------------
extern "C" void kernel_launch(void* const* d_in, const int* in_sizes, int n_in,
                              void* d_out, int out_size) {
    const float* x = (const float*)d_in[0];
    const float* Wq = (const float*)d_in[1];
    const float* Wk = (const float*)d_in[2];
    const float* Wv = (const float*)d_in[3];
    float* out = (float*)d_out;

    cudaFuncSetAttribute(proj_kernel, cudaFuncAttributeMaxDynamicSharedMemorySize, SMEM_NN);
    cudaFuncSetAttribute(scores_kernel, cudaFuncAttributeMaxDynamicSharedMemorySize, SMEM_NT);
    cudaFuncSetAttribute(pv_kernel, cudaFuncAttributeMaxDynamicSharedMemorySize, SMEM_NN);

    // 1) Fused QKV projections
    proj_kernel<<<dim3(24, 64, 1), NTHREADS, SMEM_NN>>>(x, Wq, Wk, Wv);

    // 2) Causal scores (tile-skipped)
    scores_kernel<<<dim3(SEQ / BN, SEQ / BM, BATCH), NTHREADS, SMEM_NT>>>();

    // 3) Row softmax
    softmax_kernel<<<BATCH * SEQ, 256>>>();

    // 4) O = P @ V (causal K-limit)
    pv_kernel<<<dim3(DIM / BN, SEQ / BM, BATCH), NTHREADS, SMEM_NN>>>(out);
}